// round 13
// baseline (speedup 1.0000x reference)
#include <cuda_runtime.h>
#include <cuda_bf16.h>
#include <cstdint>

#define S_LEN 2048
#define B_SZ  512
#define HID   64
#define NGATE 256
#define ROWS  4
#define NCTA  (B_SZ / ROWS)   // 128
#define NTHR  1024            // 4 K-quarters x 256 gates

// Inter-layer hidden state sequences (S, B, H) fp32, flattened row m = t*B + b.
__device__ float g_seq0[S_LEN * B_SZ * HID];
__device__ float g_seq1[S_LEN * B_SZ * HID];
// Precomputed input projections (S, B, 4H) fp32.
__device__ float g_proj[S_LEN * B_SZ * NGATE];

__device__ __forceinline__ float sigm_f(float x) {
    float e = __expf(-x);
    return __fdividef(1.0f, 1.0f + e);
}
__device__ __forceinline__ float tanh_f(float x) {
    float a = fabsf(x);
    float e = __expf(-2.0f * a);
    float t = __fdividef(1.0f - e, 1.0f + e);
    return copysignf(t, x);
}

// ===========================================================================
// Projection GEMM (unchanged, known-good): g_proj = in_seq @ W^T
// bf16x3 split on tensor cores, fp32 register accumulators.
// ===========================================================================
#define PM       64
#define WSTRIDE  66
#define SMEM_PROJ ((2 * 256 + 2 * PM) * WSTRIDE * 2)

__device__ __forceinline__ void mma16816(float c[4], uint32_t a0, uint32_t a1,
                                         uint32_t a2, uint32_t a3,
                                         uint32_t b0, uint32_t b1) {
    asm volatile(
        "mma.sync.aligned.m16n8k16.row.col.f32.bf16.bf16.f32 "
        "{%0,%1,%2,%3},{%4,%5,%6,%7},{%8,%9},{%0,%1,%2,%3};"
        : "+f"(c[0]), "+f"(c[1]), "+f"(c[2]), "+f"(c[3])
        : "r"(a0), "r"(a1), "r"(a2), "r"(a3), "r"(b0), "r"(b1));
}

template <int SRC>
__global__ __launch_bounds__(256)
void proj_gemm_kernel(const float* __restrict__ Wih)
{
    extern __shared__ __nv_bfloat16 sm[];
    __nv_bfloat16* Whi = sm;
    __nv_bfloat16* Wlo = Whi + 256 * WSTRIDE;
    __nv_bfloat16* Ahi = Wlo + 256 * WSTRIDE;
    __nv_bfloat16* Alo = Ahi + PM * WSTRIDE;

    const float* in_seq = (SRC == 0) ? g_seq0 : g_seq1;
    const int tid = threadIdx.x;
    const int m0  = blockIdx.x * PM;

    for (int i = tid; i < 256 * 64; i += 256) {
        int n = i >> 6, k = i & 63;
        float w = Wih[i];
        __nv_bfloat16 hi = __float2bfloat16_rn(w);
        Whi[n * WSTRIDE + k] = hi;
        Wlo[n * WSTRIDE + k] = __float2bfloat16_rn(w - __bfloat162float(hi));
    }
    for (int i = tid; i < PM * 64; i += 256) {
        int m = i >> 6, k = i & 63;
        float a = in_seq[(size_t)(m0 + m) * HID + k];
        __nv_bfloat16 hi = __float2bfloat16_rn(a);
        Ahi[m * WSTRIDE + k] = hi;
        Alo[m * WSTRIDE + k] = __float2bfloat16_rn(a - __bfloat162float(hi));
    }
    __syncthreads();

    const int wid = tid >> 5, lane = tid & 31;
    const int wm = (wid & 3) * 16;
    const int wn = (wid >> 2) * 128;
    const int arow = lane >> 2;
    const int kq   = (lane & 3) * 2;
    const int bn   = lane >> 2;

    float acc[16][4];
    #pragma unroll
    for (int nt = 0; nt < 16; nt++)
        #pragma unroll
        for (int i = 0; i < 4; i++) acc[nt][i] = 0.0f;

    const __nv_bfloat16* Asrc[3] = {Ahi, Ahi, Alo};
    const __nv_bfloat16* Bsrc[3] = {Whi, Wlo, Whi};

    #pragma unroll
    for (int term = 0; term < 3; term++) {
        const __nv_bfloat16* A = Asrc[term];
        const __nv_bfloat16* B = Bsrc[term];
        #pragma unroll
        for (int kc = 0; kc < 4; kc++) {
            const int k0 = kc * 16;
            uint32_t a0 = *(const uint32_t*)&A[(wm + arow    ) * WSTRIDE + k0 + kq];
            uint32_t a1 = *(const uint32_t*)&A[(wm + arow + 8) * WSTRIDE + k0 + kq];
            uint32_t a2 = *(const uint32_t*)&A[(wm + arow    ) * WSTRIDE + k0 + kq + 8];
            uint32_t a3 = *(const uint32_t*)&A[(wm + arow + 8) * WSTRIDE + k0 + kq + 8];
            #pragma unroll
            for (int nt = 0; nt < 16; nt++) {
                const int n = wn + nt * 8 + bn;
                uint32_t b0 = *(const uint32_t*)&B[n * WSTRIDE + k0 + kq];
                uint32_t b1 = *(const uint32_t*)&B[n * WSTRIDE + k0 + kq + 8];
                mma16816(acc[nt], a0, a1, a2, a3, b0, b1);
            }
        }
    }

    const int mrow = m0 + wm + (lane >> 2);
    const int ncol0 = wn + (lane & 3) * 2;
    #pragma unroll
    for (int nt = 0; nt < 16; nt++) {
        const int nc = ncol0 + nt * 8;
        *(float2*)&g_proj[(size_t)mrow * NGATE + nc] =
            make_float2(acc[nt][0], acc[nt][1]);
        *(float2*)&g_proj[(size_t)(mrow + 8) * NGATE + nc] =
            make_float2(acc[nt][2], acc[nt][3]);
    }
}

// ===========================================================================
// Layer 0: external x (B, S, 4), K split across 4 thread-quarters, 1024 thr.
// ===========================================================================
__global__ __launch_bounds__(NTHR, 1)
void lstm_l0_kernel(const float* __restrict__ x_ext,
                    const float* __restrict__ Wih,
                    const float* __restrict__ Whh,
                    const float* __restrict__ bih,
                    const float* __restrict__ bhh)
{
    const int tid = threadIdx.x;
    const int g   = tid & 255;      // gate index
    const int kq  = tid >> 8;       // K-quarter: k in [16*kq, 16*kq+16)
    const int b0  = blockIdx.x * ROWS;

    __shared__ __align__(16) float h_s[ROWS][HID];
    __shared__ __align__(16) float x_s[2][ROWS][4];
    __shared__ float gates_s[4][ROWS][NGATE];

    float whh[16];
    #pragma unroll
    for (int j = 0; j < 16; j++) whh[j] = Whh[g * HID + kq * 16 + j];
    float wih[4];
    #pragma unroll
    for (int j = 0; j < 4; j++) wih[j] = Wih[g * 4 + j];
    const float bsum = (kq == 0) ? (bih[g] + bhh[g]) : 0.0f;

    const int urow = (tid & 255) >> 6, uj = tid & 63;
    if (tid < 256) h_s[urow][uj] = 0.0f;
    float c_reg = 0.0f;

    const bool xi_act = (tid < ROWS * 4);
    const int  xi_row = tid >> 2;
    const int  xi_k   = tid & 3;
    auto load_x = [&](int t) -> float {
        return xi_act ? x_ext[(size_t)(b0 + xi_row) * (S_LEN * 4) + t * 4 + xi_k]
                      : 0.0f;
    };
    if (xi_act) x_s[0][xi_row][xi_k] = load_x(0);
    __syncthreads();

    for (int t = 0; t < S_LEN; t++) {
        const int par = t & 1;
        float x_next = (t + 1 < S_LEN) ? load_x(t + 1) : 0.0f;

        float acc[ROWS];
        #pragma unroll
        for (int r = 0; r < ROWS; r++) {
            acc[r] = bsum;
            if (kq == 0) {
                float4 x4 = *reinterpret_cast<const float4*>(&x_s[par][r][0]);
                acc[r] = fmaf(wih[0], x4.x, acc[r]);
                acc[r] = fmaf(wih[1], x4.y, acc[r]);
                acc[r] = fmaf(wih[2], x4.z, acc[r]);
                acc[r] = fmaf(wih[3], x4.w, acc[r]);
            }
        }
        #pragma unroll
        for (int j = 0; j < 16; j += 4) {
            #pragma unroll
            for (int r = 0; r < ROWS; r++) {
                float4 h4 = *reinterpret_cast<const float4*>(&h_s[r][kq * 16 + j]);
                acc[r] = fmaf(whh[j + 0], h4.x, acc[r]);
                acc[r] = fmaf(whh[j + 1], h4.y, acc[r]);
                acc[r] = fmaf(whh[j + 2], h4.z, acc[r]);
                acc[r] = fmaf(whh[j + 3], h4.w, acc[r]);
            }
        }
        #pragma unroll
        for (int r = 0; r < ROWS; r++) gates_s[kq][r][g] = acc[r];
        __syncthreads();

        if (tid < 256) {
            float gi = 0.f, gf = 0.f, gg = 0.f, go = 0.f;
            #pragma unroll
            for (int q = 0; q < 4; q++) {
                gi += gates_s[q][urow][0 * HID + uj];
                gf += gates_s[q][urow][1 * HID + uj];
                gg += gates_s[q][urow][2 * HID + uj];
                go += gates_s[q][urow][3 * HID + uj];
            }
            float iv = sigm_f(gi), fv = sigm_f(gf), gv = tanh_f(gg), ov = sigm_f(go);
            c_reg = fmaf(fv, c_reg, iv * gv);
            float hv = ov * tanh_f(c_reg);
            h_s[urow][uj] = hv;
            g_seq0[(size_t)(t * B_SZ + b0 + urow) * HID + uj] = hv;
        }
        if (xi_act) x_s[par ^ 1][xi_row][xi_k] = x_next;
        __syncthreads();
    }
}

// ===========================================================================
// Layers 1/2: recurrent-only, K split across 4 thread-quarters, 1024 threads.
// DST: 0 -> g_seq0, 1 -> g_seq1, 2 -> none. FINAL fuses the FC.
// ===========================================================================
template <int DST, bool FINAL>
__global__ __launch_bounds__(NTHR, 1)
void lstm_rec_kernel(const float* __restrict__ Whh,
                     const float* __restrict__ bih,
                     const float* __restrict__ bhh,
                     const float* __restrict__ fc_w,
                     const float* __restrict__ fc_b,
                     float* __restrict__ out_fc)
{
    const int tid = threadIdx.x;
    const int g   = tid & 255;
    const int kq  = tid >> 8;
    const int b0  = blockIdx.x * ROWS;
    float* out_seq = (DST == 0) ? g_seq0 : (DST == 1) ? g_seq1 : nullptr;

    __shared__ __align__(16) float h_s[ROWS][HID];
    __shared__ float gates_s[4][ROWS][NGATE];

    float whh[16];
    #pragma unroll
    for (int j = 0; j < 16; j++) whh[j] = Whh[g * HID + kq * 16 + j];
    const float bsum = (kq == 0) ? (bih[g] + bhh[g]) : 0.0f;

    const int urow = (tid & 255) >> 6, uj = tid & 63;
    if (tid < 256) h_s[urow][uj] = 0.0f;
    float c_reg = 0.0f;

    // distance-1 register prefetch of the precomputed projection (quarter 0)
    float p_pref[ROWS];
    #pragma unroll
    for (int r = 0; r < ROWS; r++)
        p_pref[r] = (kq == 0) ? g_proj[(size_t)(b0 + r) * NGATE + g] : 0.0f;
    __syncthreads();

    for (int t = 0; t < S_LEN; t++) {
        float acc[ROWS];
        #pragma unroll
        for (int r = 0; r < ROWS; r++) acc[r] = p_pref[r] + bsum;
        if (kq == 0 && t + 1 < S_LEN) {
            #pragma unroll
            for (int r = 0; r < ROWS; r++)
                p_pref[r] = g_proj[(size_t)((t + 1) * B_SZ + b0 + r) * NGATE + g];
        }

        #pragma unroll
        for (int j = 0; j < 16; j += 4) {
            #pragma unroll
            for (int r = 0; r < ROWS; r++) {
                float4 h4 = *reinterpret_cast<const float4*>(&h_s[r][kq * 16 + j]);
                acc[r] = fmaf(whh[j + 0], h4.x, acc[r]);
                acc[r] = fmaf(whh[j + 1], h4.y, acc[r]);
                acc[r] = fmaf(whh[j + 2], h4.z, acc[r]);
                acc[r] = fmaf(whh[j + 3], h4.w, acc[r]);
            }
        }
        #pragma unroll
        for (int r = 0; r < ROWS; r++) gates_s[kq][r][g] = acc[r];
        __syncthreads();

        if (tid < 256) {
            float gi = 0.f, gf = 0.f, gg = 0.f, go = 0.f;
            #pragma unroll
            for (int q = 0; q < 4; q++) {
                gi += gates_s[q][urow][0 * HID + uj];
                gf += gates_s[q][urow][1 * HID + uj];
                gg += gates_s[q][urow][2 * HID + uj];
                go += gates_s[q][urow][3 * HID + uj];
            }
            float iv = sigm_f(gi), fv = sigm_f(gf), gv = tanh_f(gg), ov = sigm_f(go);
            c_reg = fmaf(fv, c_reg, iv * gv);
            float hv = ov * tanh_f(c_reg);
            h_s[urow][uj] = hv;
            if (DST != 2)
                out_seq[(size_t)(t * B_SZ + b0 + urow) * HID + uj] = hv;
        }
        __syncthreads();
    }

    if (FINAL) {
        if (tid < ROWS * 2) {
            int r = tid >> 1, o = tid & 1;
            float s = fc_b[o];
            #pragma unroll
            for (int j = 0; j < HID; j++)
                s = fmaf(h_s[r][j], fc_w[o * HID + j], s);
            out_fc[(b0 + r) * 2 + o] = s;
        }
    }
}

extern "C" void kernel_launch(void* const* d_in, const int* in_sizes, int n_in,
                              void* d_out, int out_size)
{
    const float* x    = (const float*)d_in[0];
    const float* Wih0 = (const float*)d_in[1];
    const float* Whh0 = (const float*)d_in[2];
    const float* bih0 = (const float*)d_in[3];
    const float* bhh0 = (const float*)d_in[4];
    const float* Wih1 = (const float*)d_in[5];
    const float* Whh1 = (const float*)d_in[6];
    const float* bih1 = (const float*)d_in[7];
    const float* bhh1 = (const float*)d_in[8];
    const float* Wih2 = (const float*)d_in[9];
    const float* Whh2 = (const float*)d_in[10];
    const float* bih2 = (const float*)d_in[11];
    const float* bhh2 = (const float*)d_in[12];
    const float* fc_w = (const float*)d_in[13];
    const float* fc_b = (const float*)d_in[14];
    float* out = (float*)d_out;

    cudaFuncSetAttribute(proj_gemm_kernel<0>,
                         cudaFuncAttributeMaxDynamicSharedMemorySize, SMEM_PROJ);
    cudaFuncSetAttribute(proj_gemm_kernel<1>,
                         cudaFuncAttributeMaxDynamicSharedMemorySize, SMEM_PROJ);

    const int nproj = (S_LEN * B_SZ) / PM;   // 16384

    lstm_l0_kernel<<<NCTA, NTHR>>>(x, Wih0, Whh0, bih0, bhh0);
    proj_gemm_kernel<0><<<nproj, 256, SMEM_PROJ>>>(Wih1);
    lstm_rec_kernel<1, false><<<NCTA, NTHR>>>(Whh1, bih1, bhh1,
                                              nullptr, nullptr, nullptr);
    proj_gemm_kernel<1><<<nproj, 256, SMEM_PROJ>>>(Wih2);
    lstm_rec_kernel<2, true><<<NCTA, NTHR>>>(Whh2, bih2, bhh2,
                                             fc_w, fc_b, out);
}

// round 14
// speedup vs baseline: 1.3818x; 1.3818x over previous
#include <cuda_runtime.h>
#include <cuda_bf16.h>
#include <cstdint>

#define S_LEN 2048
#define B_SZ  512
#define HID   64
#define ROWS  4
#define NCTA  128
#define NTHR  512
#define HSTRIDE 152    // padded bf16 stride of A rows (conflict-free ldmatrix)
#define GSTRIDE 264    // padded fp32 stride of gates rows

// Inter-layer hidden state sequences (S, B, H) fp32.
__device__ float g_seq0[S_LEN * B_SZ * HID];
__device__ float g_seq1[S_LEN * B_SZ * HID];

__device__ __forceinline__ float sigm_f(float x) {
    float e = __expf(-x);
    return __fdividef(1.0f, 1.0f + e);
}
__device__ __forceinline__ float tanh_f(float x) {
    float a = fabsf(x);
    float e = __expf(-2.0f * a);
    float t = __fdividef(1.0f - e, 1.0f + e);
    return copysignf(t, x);
}

__device__ __forceinline__ uint32_t smem_u32(const void* p) {
    uint32_t a;
    asm("{ .reg .u64 t; cvta.to.shared.u64 t, %1; cvt.u32.u64 %0, t; }"
        : "=r"(a) : "l"(p));
    return a;
}
__device__ __forceinline__ void ldsm4(uint32_t& r0, uint32_t& r1,
                                      uint32_t& r2, uint32_t& r3, uint32_t a) {
    asm volatile("ldmatrix.sync.aligned.m8n8.x4.shared.b16 {%0,%1,%2,%3}, [%4];"
        : "=r"(r0), "=r"(r1), "=r"(r2), "=r"(r3) : "r"(a));
}
__device__ __forceinline__ void mma16816(float c[4], uint32_t a0, uint32_t a1,
                                         uint32_t a2, uint32_t a3,
                                         uint32_t b0, uint32_t b1) {
    asm volatile(
        "mma.sync.aligned.m16n8k16.row.col.f32.bf16.bf16.f32 "
        "{%0,%1,%2,%3},{%4,%5,%6,%7},{%8,%9},{%0,%1,%2,%3};"
        : "+f"(c[0]), "+f"(c[1]), "+f"(c[2]), "+f"(c[3])
        : "r"(a0), "r"(a1), "r"(a2), "r"(a3), "r"(b0), "r"(b1));
}
// Split (f0,f1) into packed bf16 hi pair (returned) and lo pair (out-param).
__device__ __forceinline__ uint32_t packsplit(float f0, float f1, uint32_t& lo) {
    __nv_bfloat162 h = __floats2bfloat162_rn(f0, f1);
    float r0 = f0 - __bfloat162float(h.x);
    float r1 = f1 - __bfloat162float(h.y);
    __nv_bfloat162 l = __floats2bfloat162_rn(r0, r1);
    lo = *reinterpret_cast<uint32_t*>(&l);
    return *reinterpret_cast<uint32_t*>(&h);
}

// KC: number of K=16 chunks (5 for L0 [64h+4x+pad], 8 for L1/2 [64h+64x]).
// SRC: 0/1 -> g_seq0/1 (prev layer h), 2 -> external x (B,S,4).
// DST: 0/1 -> g_seq0/1, 2 -> none. FINAL fuses the FC.
template <int KC, int IN, int SRC, int DST, bool FINAL>
__global__ __launch_bounds__(NTHR, 1)
void lstm_mma_kernel(const float* __restrict__ x_ext,
                     const float* __restrict__ Wih,
                     const float* __restrict__ Whh,
                     const float* __restrict__ bih,
                     const float* __restrict__ bhh,
                     const float* __restrict__ fc_w,
                     const float* __restrict__ fc_b,
                     float* __restrict__ out_fc)
{
    const int tid  = threadIdx.x;
    const int w    = tid >> 5, lane = tid & 31;
    const int b0   = blockIdx.x * ROWS;
    const float* seq_in  = (SRC == 0) ? g_seq0 : g_seq1;
    float*       seq_out = (DST == 0) ? g_seq0 : (DST == 1) ? g_seq1 : nullptr;

    // A operand: [h(64) | x] bf16 hi/lo, double-buffered, 16 M-rows (4 real).
    __shared__ __nv_bfloat16 Ahi[2][16][HSTRIDE];
    __shared__ __nv_bfloat16 Alo[2][16][HSTRIDE];
    __shared__ float gts[ROWS][GSTRIDE];
    __shared__ float hf[ROWS][HID];

    // --- B fragments (weights) in registers: warp w owns gates [16w,16w+16) ---
    uint32_t bhi[2][KC][2], blo[2][KC][2];
    float bias0[2], bias1[2];
    #pragma unroll
    for (int nt = 0; nt < 2; nt++) {
        const int n = w * 16 + nt * 8 + (lane >> 2);
        #pragma unroll
        for (int kc = 0; kc < KC; kc++) {
            #pragma unroll
            for (int j = 0; j < 2; j++) {
                const int k0 = kc * 16 + (lane & 3) * 2 + j * 8;   // even, no straddle
                float f0 = (k0 < HID) ? Whh[n * HID + k0]
                          : ((k0 - HID) < IN ? Wih[n * IN + (k0 - HID)] : 0.0f);
                float f1 = (k0 + 1 < HID) ? Whh[n * HID + k0 + 1]
                          : ((k0 + 1 - HID) < IN ? Wih[n * IN + (k0 + 1 - HID)] : 0.0f);
                bhi[nt][kc][j] = packsplit(f0, f1, blo[nt][kc][j]);
            }
        }
        const int nc = w * 16 + nt * 8 + (lane & 3) * 2;
        bias0[nt] = bih[nc] + bhh[nc];
        bias1[nt] = bih[nc + 1] + bhh[nc + 1];
    }

    const int urow = tid >> 6, uj = tid & 63;   // update map (tid < 256)
    float c_reg = 0.0f;

    // --- init: h_{-1}=0 in buf0, stage x(0), zero L0 K-padding ---
    if (tid < 256) {
        Ahi[0][urow][uj] = __float2bfloat16_rn(0.0f);
        Alo[0][urow][uj] = __float2bfloat16_rn(0.0f);
    }
    if (SRC == 2) {
        if (tid < 16) {
            int r = tid >> 2, c = tid & 3;
            float xv = x_ext[(size_t)(b0 + r) * (S_LEN * 4) + c];
            __nv_bfloat16 xh = __float2bfloat16_rn(xv);
            Ahi[0][r][64 + c] = xh;
            Alo[0][r][64 + c] = __float2bfloat16_rn(xv - __bfloat162float(xh));
        }
        if (tid < 96) {   // zero pad cols 68..79, rows 0-3, both buffers
            int bb = tid / 48, rr = (tid / 12) % 4, cc = 68 + tid % 12;
            Ahi[bb][rr][cc] = __float2bfloat16_rn(0.0f);
            Alo[bb][rr][cc] = __float2bfloat16_rn(0.0f);
        }
    } else {
        if (tid < 256) {
            float xv = seq_in[(size_t)(b0 + urow) * HID + uj];
            __nv_bfloat16 xh = __float2bfloat16_rn(xv);
            Ahi[0][urow][64 + uj] = xh;
            Alo[0][urow][64 + uj] = __float2bfloat16_rn(xv - __bfloat162float(xh));
        }
    }
    __syncthreads();

    // ldmatrix lane addressing (quads: rows0-7/rows8-15 x col+0/col+8)
    const int lrow  = (lane & 7) + ((lane >> 3) & 1) * 8;
    const int lcolb = (lane >> 4) * 16;                    // bytes
    const uint32_t ahi_b = smem_u32(&Ahi[0][0][0]);
    const uint32_t alo_b = smem_u32(&Alo[0][0][0]);
    const uint32_t aoff  = lrow * (HSTRIDE * 2) + lcolb;
    const uint32_t BUFB  = 16 * HSTRIDE * 2;

    for (int t = 0; t < S_LEN; t++) {
        const int rb = t & 1, wb = rb ^ 1;

        // prefetch next x into registers (latency hidden under MMA)
        float xv = 0.0f;
        const int tn = (t + 1 < S_LEN) ? (t + 1) : t;
        if (SRC == 2) {
            if (tid < 16) {
                int r = tid >> 2, c = tid & 3;
                xv = x_ext[(size_t)(b0 + r) * (S_LEN * 4) + tn * 4 + c];
            }
        } else {
            if (tid < 256)
                xv = seq_in[(size_t)(tn * B_SZ + b0 + urow) * HID + uj];
        }

        // --- gates = bias + [h|x] @ W_cat^T  (bf16x3: hh + hl + lh) ---
        float d[2][4];
        #pragma unroll
        for (int nt = 0; nt < 2; nt++) {
            d[nt][0] = bias0[nt]; d[nt][1] = bias1[nt];
            d[nt][2] = 0.0f;      d[nt][3] = 0.0f;      // pad rows, never read
        }
        #pragma unroll
        for (int kc = 0; kc < KC; kc++) {
            uint32_t ah0, ah1, ah2, ah3, al0, al1, al2, al3;
            ldsm4(ah0, ah1, ah2, ah3, ahi_b + rb * BUFB + aoff + kc * 32);
            ldsm4(al0, al1, al2, al3, alo_b + rb * BUFB + aoff + kc * 32);
            #pragma unroll
            for (int nt = 0; nt < 2; nt++) {
                mma16816(d[nt], ah0, ah1, ah2, ah3, bhi[nt][kc][0], bhi[nt][kc][1]);
                mma16816(d[nt], ah0, ah1, ah2, ah3, blo[nt][kc][0], blo[nt][kc][1]);
                mma16816(d[nt], al0, al1, al2, al3, bhi[nt][kc][0], bhi[nt][kc][1]);
            }
        }
        // store real D rows (0-3) to gates smem
        if (lane < 16) {
            const int r = lane >> 2;
            #pragma unroll
            for (int nt = 0; nt < 2; nt++) {
                const int col = w * 16 + nt * 8 + (lane & 3) * 2;
                *(float2*)&gts[r][col] = make_float2(d[nt][0], d[nt][1]);
            }
        }
        __syncthreads();

        // --- state update (R1-proven shape: 1 elem/thread, c in register) ---
        if (tid < 256) {
            float gi = gts[urow][uj];
            float gf = gts[urow][64 + uj];
            float gg = gts[urow][128 + uj];
            float go = gts[urow][192 + uj];
            float iv = sigm_f(gi), fv = sigm_f(gf), gv = tanh_f(gg), ov = sigm_f(go);
            c_reg = fmaf(fv, c_reg, iv * gv);
            float hv = ov * tanh_f(c_reg);

            __nv_bfloat16 hh = __float2bfloat16_rn(hv);
            Ahi[wb][urow][uj] = hh;
            Alo[wb][urow][uj] = __float2bfloat16_rn(hv - __bfloat162float(hh));
            if (FINAL) hf[urow][uj] = hv;
            if (DST != 2)
                seq_out[(size_t)(t * B_SZ + b0 + urow) * HID + uj] = hv;

            // stage prefetched x(t+1) into the write buffer
            if (SRC == 2) {
                if (tid < 16) {
                    int r = tid >> 2, c = tid & 3;
                    __nv_bfloat16 xh = __float2bfloat16_rn(xv);
                    Ahi[wb][r][64 + c] = xh;
                    Alo[wb][r][64 + c] = __float2bfloat16_rn(xv - __bfloat162float(xh));
                }
            } else {
                __nv_bfloat16 xh = __float2bfloat16_rn(xv);
                Ahi[wb][urow][64 + uj] = xh;
                Alo[wb][urow][64 + uj] = __float2bfloat16_rn(xv - __bfloat162float(xh));
            }
        }
        __syncthreads();
    }

    if (FINAL) {
        if (tid < ROWS * 2) {
            int r = tid >> 1, o = tid & 1;
            float s = fc_b[o];
            #pragma unroll
            for (int j = 0; j < HID; j++)
                s = fmaf(hf[r][j], fc_w[o * HID + j], s);
            out_fc[(b0 + r) * 2 + o] = s;
        }
    }
}

extern "C" void kernel_launch(void* const* d_in, const int* in_sizes, int n_in,
                              void* d_out, int out_size)
{
    const float* x    = (const float*)d_in[0];
    const float* Wih0 = (const float*)d_in[1];
    const float* Whh0 = (const float*)d_in[2];
    const float* bih0 = (const float*)d_in[3];
    const float* bhh0 = (const float*)d_in[4];
    const float* Wih1 = (const float*)d_in[5];
    const float* Whh1 = (const float*)d_in[6];
    const float* bih1 = (const float*)d_in[7];
    const float* bhh1 = (const float*)d_in[8];
    const float* Wih2 = (const float*)d_in[9];
    const float* Whh2 = (const float*)d_in[10];
    const float* bih2 = (const float*)d_in[11];
    const float* bhh2 = (const float*)d_in[12];
    const float* fc_w = (const float*)d_in[13];
    const float* fc_b = (const float*)d_in[14];
    float* out = (float*)d_out;

    // layer 0: K = 64h + 4x (pad to 80), external x -> g_seq0
    lstm_mma_kernel<5, 4, 2, 0, false><<<NCTA, NTHR>>>(
        x, Wih0, Whh0, bih0, bhh0, nullptr, nullptr, nullptr);
    // layer 1: K = 64h + 64x (x = g_seq0) -> g_seq1
    lstm_mma_kernel<8, 64, 0, 1, false><<<NCTA, NTHR>>>(
        nullptr, Wih1, Whh1, bih1, bhh1, nullptr, nullptr, nullptr);
    // layer 2: K = 128 (x = g_seq1), no seq store, fused FC -> out
    lstm_mma_kernel<8, 64, 1, 2, true><<<NCTA, NTHR>>>(
        nullptr, Wih2, Whh2, bih2, bhh2, fc_w, fc_b, out);
}

// round 16
// speedup vs baseline: 1.7623x; 1.2754x over previous
#include <cuda_runtime.h>
#include <cuda_bf16.h>
#include <cstdint>

#define S_LEN 2048
#define B_SZ  512
#define HID   64
#define ROWS  8
#define NCTA  64
#define NTHR  512
#define HSTRIDE 136   // bf16 stride of A_s rows: 4n+j bank map, conflict-free
#define GSN   9       // fp32 stride of gtsT rows: 9j mod 32 distinct

// Inter-layer hidden state sequences (S, B, H) fp32.
__device__ float g_seq0[S_LEN * B_SZ * HID];
__device__ float g_seq1[S_LEN * B_SZ * HID];

__device__ __forceinline__ float sigm_f(float x) {
    float e = __expf(-x);
    return __fdividef(1.0f, 1.0f + e);
}
__device__ __forceinline__ float tanh_f(float x) {
    float a = fabsf(x);
    float e = __expf(-2.0f * a);
    float t = __fdividef(1.0f - e, 1.0f + e);
    return copysignf(t, x);
}
__device__ __forceinline__ void mma16816(float c[4], uint32_t a0, uint32_t a1,
                                         uint32_t a2, uint32_t a3,
                                         uint32_t b0, uint32_t b1) {
    asm volatile(
        "mma.sync.aligned.m16n8k16.row.col.f32.bf16.bf16.f32 "
        "{%0,%1,%2,%3},{%4,%5,%6,%7},{%8,%9},{%0,%1,%2,%3};"
        : "+f"(c[0]), "+f"(c[1]), "+f"(c[2]), "+f"(c[3])
        : "r"(a0), "r"(a1), "r"(a2), "r"(a3), "r"(b0), "r"(b1));
}
// Split (f0,f1) into packed bf16 hi pair (returned) and lo pair (out-param).
__device__ __forceinline__ uint32_t packsplit(float f0, float f1, uint32_t& lo) {
    __nv_bfloat162 h = __floats2bfloat162_rn(f0, f1);
    float r0 = f0 - __bfloat162float(h.x);
    float r1 = f1 - __bfloat162float(h.y);
    __nv_bfloat162 l = __floats2bfloat162_rn(r0, r1);
    lo = *reinterpret_cast<uint32_t*>(&l);
    return *reinterpret_cast<uint32_t*>(&h);
}

// Transposed decomposition: D[256 gates x 8 rows] = W_cat[256 x K] @ [h|x]^T.
// Warp w owns gates [16w, 16w+16): A-frags = weights (registers, hi/lo),
// B-frags = activations, read as plain 32-bit LDS from A_s[row][k].
// KC: K/16 chunks (5 for L0: 64h+4x+pad, 8 for L1/2: 64h+64x).
// SRC: 0/1 -> g_seq0/1 (prev layer h), 2 -> external x (B,S,4).
// DST: 0/1 -> g_seq0/1, 2 -> none. FINAL fuses the FC.
template <int KC, int IN, int SRC, int DST, bool FINAL>
__global__ __launch_bounds__(NTHR, 1)
void lstm_mma_kernel(const float* __restrict__ x_ext,
                     const float* __restrict__ Wih,
                     const float* __restrict__ Whh,
                     const float* __restrict__ bih,
                     const float* __restrict__ bhh,
                     const float* __restrict__ fc_w,
                     const float* __restrict__ fc_b,
                     float* __restrict__ out_fc)
{
    const int tid  = threadIdx.x;
    const int w    = tid >> 5, lane = tid & 31;
    const int b0   = blockIdx.x * ROWS;
    const float* seq_in  = (SRC == 0) ? g_seq0 : g_seq1;
    float*       seq_out = (DST == 0) ? g_seq0 : (DST == 1) ? g_seq1 : nullptr;

    // Activations [h(64) | x] bf16 hi/lo, [row][k], double-buffered.
    __shared__ __nv_bfloat16 Ahi[2][ROWS][HSTRIDE];
    __shared__ __nv_bfloat16 Alo[2][ROWS][HSTRIDE];
    __shared__ float gts[256][GSN];   // gates transposed: [gate][row]
    __shared__ float hf[ROWS][HID];

    // --- weight A-frags in registers (proven R8 A-frag addressing) ---
    const int gr = w * 16 + (lane >> 2);      // gate row of c0/c1
    uint32_t ahi[KC][4], alo[KC][4];
    {
        auto wval = [&](int g, int k) -> float {
            if (k < HID) return Whh[g * HID + k];
            int kk = k - HID;
            return (kk < IN) ? Wih[g * IN + kk] : 0.0f;
        };
        #pragma unroll
        for (int kc = 0; kc < KC; kc++) {
            const int k0 = kc * 16 + (lane & 3) * 2;
            ahi[kc][0] = packsplit(wval(gr,     k0    ), wval(gr,     k0 + 1), alo[kc][0]);
            ahi[kc][1] = packsplit(wval(gr + 8, k0    ), wval(gr + 8, k0 + 1), alo[kc][1]);
            ahi[kc][2] = packsplit(wval(gr,     k0 + 8), wval(gr,     k0 + 9), alo[kc][2]);
            ahi[kc][3] = packsplit(wval(gr + 8, k0 + 8), wval(gr + 8, k0 + 9), alo[kc][3]);
        }
    }
    const float bias0 = bih[gr] + bhh[gr];
    const float bias1 = bih[gr + 8] + bhh[gr + 8];

    // update/staging map: every thread owns one (row, j) element
    const int urow = tid >> 6, uj = tid & 63;
    float c_reg = 0.0f;

    // --- init: h_{-1}=0 in buf0, stage x(0), zero L0 K-padding ---
    Ahi[0][urow][uj] = __float2bfloat16_rn(0.0f);
    Alo[0][urow][uj] = __float2bfloat16_rn(0.0f);
    if (SRC == 2) {
        if (tid < 32) {
            int r = tid >> 2, c = tid & 3;
            float xv = x_ext[(size_t)(b0 + r) * (S_LEN * 4) + c];
            __nv_bfloat16 xh = __float2bfloat16_rn(xv);
            Ahi[0][r][64 + c] = xh;
            Alo[0][r][64 + c] = __float2bfloat16_rn(xv - __bfloat162float(xh));
        }
        if (tid < 192) {   // zero pad cols 68..79, rows 0-7, both buffers
            int bb = tid / 96, rr = (tid % 96) / 12, cc = 68 + tid % 12;
            Ahi[bb][rr][cc] = __float2bfloat16_rn(0.0f);
            Alo[bb][rr][cc] = __float2bfloat16_rn(0.0f);
        }
    } else {
        float xv = seq_in[(size_t)(b0 + urow) * HID + uj];
        __nv_bfloat16 xh = __float2bfloat16_rn(xv);
        Ahi[0][urow][64 + uj] = xh;
        Alo[0][urow][64 + uj] = __float2bfloat16_rn(xv - __bfloat162float(xh));
    }
    __syncthreads();

    // B-frag addressing (proven R8 B-frag pattern): row n = lane>>2, k pair
    const int brow = lane >> 2;
    const int bk   = (lane & 3) * 2;

    for (int t = 0; t < S_LEN; t++) {
        const int rb = t & 1, wb = rb ^ 1;

        // prefetch next input into registers (latency hidden under MMA)
        const int tn = (t + 1 < S_LEN) ? (t + 1) : t;
        float xv = 0.0f;
        if (SRC == 2) {
            if (tid < 32)
                xv = x_ext[(size_t)(b0 + (tid >> 2)) * (S_LEN * 4) + tn * 4 + (tid & 3)];
        } else {
            xv = seq_in[(size_t)(tn * B_SZ + b0 + urow) * HID + uj];
        }

        // --- gates^T = bias + W_cat @ [h|x]^T (bf16x3: hh + lh + hl) ---
        float d[4] = {bias0, bias0, bias1, bias1};
        #pragma unroll
        for (int kc = 0; kc < KC; kc++) {
            const __nv_bfloat16* hb = &Ahi[rb][brow][kc * 16 + bk];
            const __nv_bfloat16* lb = &Alo[rb][brow][kc * 16 + bk];
            uint32_t bh0 = *(const uint32_t*)hb;
            uint32_t bh1 = *(const uint32_t*)(hb + 8);
            uint32_t bl0 = *(const uint32_t*)lb;
            uint32_t bl1 = *(const uint32_t*)(lb + 8);
            mma16816(d, ahi[kc][0], ahi[kc][1], ahi[kc][2], ahi[kc][3], bh0, bh1);
            mma16816(d, alo[kc][0], alo[kc][1], alo[kc][2], alo[kc][3], bh0, bh1);
            mma16816(d, ahi[kc][0], ahi[kc][1], ahi[kc][2], ahi[kc][3], bl0, bl1);
        }
        // D store: c0/c1 -> (gate gr, rows bk,bk+1); c2/c3 -> gate gr+8
        gts[gr][bk]         = d[0];
        gts[gr][bk + 1]     = d[1];
        gts[gr + 8][bk]     = d[2];
        gts[gr + 8][bk + 1] = d[3];
        __syncthreads();

        // --- state update: all 512 threads, 1 elem each, c in register ---
        {
            float gi = gts[uj][urow];
            float gf = gts[64 + uj][urow];
            float gg = gts[128 + uj][urow];
            float go = gts[192 + uj][urow];
            float iv = sigm_f(gi), fv = sigm_f(gf), gv = tanh_f(gg), ov = sigm_f(go);
            c_reg = fmaf(fv, c_reg, iv * gv);
            float hv = ov * tanh_f(c_reg);

            __nv_bfloat16 hh = __float2bfloat16_rn(hv);
            Ahi[wb][urow][uj] = hh;
            Alo[wb][urow][uj] = __float2bfloat16_rn(hv - __bfloat162float(hh));
            if (FINAL) hf[urow][uj] = hv;
            if (DST != 2)
                seq_out[(size_t)(t * B_SZ + b0 + urow) * HID + uj] = hv;

            // stage prefetched x(t+1) into the write buffer
            if (SRC == 2) {
                if (tid < 32) {
                    int r = tid >> 2, c = tid & 3;
                    __nv_bfloat16 xh = __float2bfloat16_rn(xv);
                    Ahi[wb][r][64 + c] = xh;
                    Alo[wb][r][64 + c] = __float2bfloat16_rn(xv - __bfloat162float(xh));
                }
            } else {
                __nv_bfloat16 xh = __float2bfloat16_rn(xv);
                Ahi[wb][urow][64 + uj] = xh;
                Alo[wb][urow][64 + uj] = __float2bfloat16_rn(xv - __bfloat162float(xh));
            }
        }
        __syncthreads();
    }

    if (FINAL) {
        if (tid < ROWS * 2) {
            int r = tid >> 1, o = tid & 1;
            float s = fc_b[o];
            #pragma unroll
            for (int j = 0; j < HID; j++)
                s = fmaf(hf[r][j], fc_w[o * HID + j], s);
            out_fc[(b0 + r) * 2 + o] = s;
        }
    }
}

extern "C" void kernel_launch(void* const* d_in, const int* in_sizes, int n_in,
                              void* d_out, int out_size)
{
    const float* x    = (const float*)d_in[0];
    const float* Wih0 = (const float*)d_in[1];
    const float* Whh0 = (const float*)d_in[2];
    const float* bih0 = (const float*)d_in[3];
    const float* bhh0 = (const float*)d_in[4];
    const float* Wih1 = (const float*)d_in[5];
    const float* Whh1 = (const float*)d_in[6];
    const float* bih1 = (const float*)d_in[7];
    const float* bhh1 = (const float*)d_in[8];
    const float* Wih2 = (const float*)d_in[9];
    const float* Whh2 = (const float*)d_in[10];
    const float* bih2 = (const float*)d_in[11];
    const float* bhh2 = (const float*)d_in[12];
    const float* fc_w = (const float*)d_in[13];
    const float* fc_b = (const float*)d_in[14];
    float* out = (float*)d_out;

    // layer 0: K = 64h + 4x (pad to 80), external x -> g_seq0
    lstm_mma_kernel<5, 4, 2, 0, false><<<NCTA, NTHR>>>(
        x, Wih0, Whh0, bih0, bhh0, nullptr, nullptr, nullptr);
    // layer 1: K = 64h + 64x (x = g_seq0) -> g_seq1
    lstm_mma_kernel<8, 64, 0, 1, false><<<NCTA, NTHR>>>(
        nullptr, Wih1, Whh1, bih1, bhh1, nullptr, nullptr, nullptr);
    // layer 2: K = 128 (x = g_seq1), no seq store, fused FC -> out
    lstm_mma_kernel<8, 64, 1, 2, true><<<NCTA, NTHR>>>(
        nullptr, Wih2, Whh2, bih2, bhh2, fc_w, fc_b, out);
}